// round 9
// baseline (speedup 1.0000x reference)
#include <cuda_runtime.h>
#include <cstdint>

// PBC neighbor-list distances. Shift rows: compute into SMEM, then TMA bulk
// store (cp.async.bulk shared->global) so the 162MB write stream bypasses the
// per-thread L1/STG port. Triangle rows: scalar STG (3.7% of bytes).
// Output (float32): [ d2[P] | mask_c0[P] | mask_c1[P] | ... ],
//   P = N*(N-1)/2 + S*N*N. All offsets fit in int32.
// TMA path requires n % 4 == 0, Pc % 4 == 0, n <= 1024 (true for this problem:
// n=1000, Pc=499500). Otherwise host falls back to the STG kernel.

#define MAXN 1024

__device__ __forceinline__ uint32_t smem_u32(const void* p) {
    return (uint32_t)__cvta_generic_to_shared(p);
}

template <int C>
__global__ __launch_bounds__(256)
void fused_tma_kernel(const float* __restrict__ pos,
                      const float* __restrict__ cell,
                      const float* __restrict__ shifts,
                      const float* __restrict__ cutoffs,
                      int n, int S, int Pc, int P,
                      float* __restrict__ out)
{
    __shared__ __align__(16) float sm[(1 + C) * MAXN];

    int i   = blockIdx.x;
    int s   = blockIdx.y;
    int tid = threadIdx.x;

    float c2[C];
#pragma unroll
    for (int c = 0; c < C; c++) { float cv = cutoffs[c]; c2[c] = cv * cv; }

    float pix = pos[3 * i + 0];
    float piy = pos[3 * i + 1];
    float piz = pos[3 * i + 2];

    if (s < S) {
        // ---------------- shifted-image row (s, i, :) ----------------
        float s0 = shifts[3 * s + 0], s1 = shifts[3 * s + 1], s2 = shifts[3 * s + 2];
        float svx = s0 * cell[0] + s1 * cell[3] + s2 * cell[6];
        float svy = s0 * cell[1] + s1 * cell[4] + s2 * cell[7];
        float svz = s0 * cell[2] + s1 * cell[5] + s2 * cell[8];

        const float4* __restrict__ pos4 = (const float4*)pos;
        int nq = n >> 2;

        for (int q = tid; q < nq; q += blockDim.x) {
            float4 a  = pos4[3 * q + 0];
            float4 b  = pos4[3 * q + 1];
            float4 cc = pos4[3 * q + 2];

            float dx, dy, dz;
            float4 dv;
            // reference FP ordering: (pi - pj) + sv
            dx = (pix - a.x) + svx;  dy = (piy - a.y) + svy;  dz = (piz - a.z) + svz;
            dv.x = dx * dx + dy * dy + dz * dz;
            dx = (pix - a.w) + svx;  dy = (piy - b.x) + svy;  dz = (piz - b.y) + svz;
            dv.y = dx * dx + dy * dy + dz * dz;
            dx = (pix - b.z) + svx;  dy = (piy - b.w) + svy;  dz = (piz - cc.x) + svz;
            dv.z = dx * dx + dy * dy + dz * dz;
            dx = (pix - cc.y) + svx; dy = (piy - cc.z) + svy; dz = (piz - cc.w) + svz;
            dv.w = dx * dx + dy * dy + dz * dz;

            *(float4*)(sm + 4 * q) = dv;

#pragma unroll
            for (int c = 0; c < C; c++) {
                float4 mv;
                mv.x = (dv.x < c2[c]) ? 1.0f : 0.0f;
                mv.y = (dv.y < c2[c]) ? 1.0f : 0.0f;
                mv.z = (dv.z < c2[c]) ? 1.0f : 0.0f;
                mv.w = (dv.w < c2[c]) ? 1.0f : 0.0f;
                *(float4*)(sm + (c + 1) * MAXN + 4 * q) = mv;
            }
        }
        __syncthreads();

        if (tid == 0) {
            asm volatile("fence.proxy.async.shared::cta;" ::: "memory");
            int rowbase = Pc + (s * n + i) * n;
            uint32_t nbytes = (uint32_t)(n * 4);

            uint32_t src0 = smem_u32(sm);
            asm volatile(
                "cp.async.bulk.global.shared::cta.bulk_group [%0], [%1], %2;"
                :: "l"(out + rowbase), "r"(src0), "r"(nbytes) : "memory");
#pragma unroll
            for (int c = 0; c < C; c++) {
                uint32_t srcc = smem_u32(sm + (c + 1) * MAXN);
                asm volatile(
                    "cp.async.bulk.global.shared::cta.bulk_group [%0], [%1], %2;"
                    :: "l"(out + P + c * P + rowbase), "r"(srcc), "r"(nbytes)
                    : "memory");
            }
            asm volatile("cp.async.bulk.commit_group;" ::: "memory");
            asm volatile("cp.async.bulk.wait_group 0;" ::: "memory");
        }
        __syncthreads();   // keep SMEM alive until TMA has read it
    } else {
        // ---------------- triangle row i: pairs (i, j), j > i ----------------
        int off = i * (2 * n - i - 1) / 2;
        for (int j = i + 1 + tid; j < n; j += blockDim.x) {
            float dx = pix - pos[3 * j + 0];
            float dy = piy - pos[3 * j + 1];
            float dz = piz - pos[3 * j + 2];
            float d2 = dx * dx + dy * dy + dz * dz;
            int p = off + (j - i - 1);
            out[p] = d2;
#pragma unroll
            for (int c = 0; c < C; c++)
                out[P + c * P + p] = (d2 < c2[c]) ? 1.0f : 0.0f;
        }
    }
}

// ---------------- fallback: per-thread STG (R8 shape) ----------------
template <int C>
__global__ __launch_bounds__(256)
void fused_stg_kernel(const float* __restrict__ pos,
                      const float* __restrict__ cell,
                      const float* __restrict__ shifts,
                      const float* __restrict__ cutoffs,
                      int n, int S, int Pc, int P,
                      float* __restrict__ out)
{
    int i = blockIdx.x, s = blockIdx.y, tid = threadIdx.x;
    float c2[C];
#pragma unroll
    for (int c = 0; c < C; c++) { float cv = cutoffs[c]; c2[c] = cv * cv; }
    float pix = pos[3 * i + 0], piy = pos[3 * i + 1], piz = pos[3 * i + 2];

    if (s < S) {
        float s0 = shifts[3 * s + 0], s1 = shifts[3 * s + 1], s2 = shifts[3 * s + 2];
        float svx = s0 * cell[0] + s1 * cell[3] + s2 * cell[6];
        float svy = s0 * cell[1] + s1 * cell[4] + s2 * cell[7];
        float svz = s0 * cell[2] + s1 * cell[5] + s2 * cell[8];
        int rowbase = Pc + (s * n + i) * n;
        for (int j = tid; j < n; j += blockDim.x) {
            float dx = (pix - pos[3 * j + 0]) + svx;
            float dy = (piy - pos[3 * j + 1]) + svy;
            float dz = (piz - pos[3 * j + 2]) + svz;
            float d2 = dx * dx + dy * dy + dz * dz;
            out[rowbase + j] = d2;
#pragma unroll
            for (int c = 0; c < C; c++)
                out[P + c * P + rowbase + j] = (d2 < c2[c]) ? 1.0f : 0.0f;
        }
    } else {
        int off = i * (2 * n - i - 1) / 2;
        for (int j = i + 1 + tid; j < n; j += blockDim.x) {
            float dx = pix - pos[3 * j + 0];
            float dy = piy - pos[3 * j + 1];
            float dz = piz - pos[3 * j + 2];
            float d2 = dx * dx + dy * dy + dz * dz;
            int p = off + (j - i - 1);
            out[p] = d2;
#pragma unroll
            for (int c = 0; c < C; c++)
                out[P + c * P + p] = (d2 < c2[c]) ? 1.0f : 0.0f;
        }
    }
}

extern "C" void kernel_launch(void* const* d_in, const int* in_sizes, int n_in,
                              void* d_out, int out_size)
{
    const float* pos     = (const float*)d_in[0];  // [N,3]
    const float* cell    = (const float*)d_in[1];  // [3,3]
    const float* shifts  = (const float*)d_in[2];  // [S,3]
    const float* cutoffs = (const float*)d_in[3];  // [C]

    int n = in_sizes[0] / 3;
    int S = in_sizes[2] / 3;
    int C = in_sizes[3];

    int Pc = n * (n - 1) / 2;
    int P  = Pc + S * n * n;

    dim3 grid(n, S + 1);
    float* out = (float*)d_out;

    bool tma_ok = (n % 4 == 0) && (Pc % 4 == 0) && (n <= MAXN) && (C >= 1) && (C <= 4);

    if (tma_ok) {
        switch (C) {
            case 1: fused_tma_kernel<1><<<grid, 256>>>(pos, cell, shifts, cutoffs, n, S, Pc, P, out); break;
            case 2: fused_tma_kernel<2><<<grid, 256>>>(pos, cell, shifts, cutoffs, n, S, Pc, P, out); break;
            case 3: fused_tma_kernel<3><<<grid, 256>>>(pos, cell, shifts, cutoffs, n, S, Pc, P, out); break;
            default: fused_tma_kernel<4><<<grid, 256>>>(pos, cell, shifts, cutoffs, n, S, Pc, P, out); break;
        }
    } else {
        switch (C) {
            case 1: fused_stg_kernel<1><<<grid, 256>>>(pos, cell, shifts, cutoffs, n, S, Pc, P, out); break;
            case 2: fused_stg_kernel<2><<<grid, 256>>>(pos, cell, shifts, cutoffs, n, S, Pc, P, out); break;
            case 3: fused_stg_kernel<3><<<grid, 256>>>(pos, cell, shifts, cutoffs, n, S, Pc, P, out); break;
            default: fused_stg_kernel<4><<<grid, 256>>>(pos, cell, shifts, cutoffs, n, S, Pc, P, out); break;
        }
    }
}

// round 10
// speedup vs baseline: 1.0801x; 1.0801x over previous
#include <cuda_runtime.h>

// PBC neighbor-list distances. Single fused launch.
// Output (float32): [ d2[P] | mask_c0[P] | mask_c1[P] | ... ]
//   P = N*(N-1)/2 + S*N*N
// gridDim = (N, S+1):
//   y = s < S : shifted row (s, i, :) — one float4 j-quad per thread.
//   y = S     : triangle pairs, load-balanced: block bx handles rows bx and
//               n-2-bx (together ~n pairs), so the slice has no straggler.
// Evidence (R1-R9): kernel time is pinned at ~26.5us by the path-independent
// chip LTS write cap (162MB of L2 sector writes); st.global.cs is kept as the
// best-measured store flavor, everything else minimized around that wall.
// All offsets fit in int32 (3P ~ 40.5M).

__device__ __forceinline__ void st_cs_v4(float* p, float4 v) {
    asm volatile("st.global.cs.v4.f32 [%0],{%1,%2,%3,%4};"
                 :: "l"(p), "f"(v.x), "f"(v.y), "f"(v.z), "f"(v.w) : "memory");
}
__device__ __forceinline__ void st_cs_f(float* p, float v) {
    asm volatile("st.global.cs.f32 [%0],%1;" :: "l"(p), "f"(v) : "memory");
}

template <int C>
__global__ __launch_bounds__(256)
void fused_kernel(const float* __restrict__ pos,
                  const float* __restrict__ cell,
                  const float* __restrict__ shifts,
                  const float* __restrict__ cutoffs,
                  int n, int S, int Pc, int P,
                  float* __restrict__ out)
{
    int bx  = blockIdx.x;
    int s   = blockIdx.y;
    int tid = threadIdx.x;

    float c2[C];
#pragma unroll
    for (int c = 0; c < C; c++) { float cv = cutoffs[c]; c2[c] = cv * cv; }

    if (s < S) {
        // ---------------- shifted-image row (s, i, :) ----------------
        int i = bx;
        float pix = pos[3 * i + 0];
        float piy = pos[3 * i + 1];
        float piz = pos[3 * i + 2];

        float s0 = shifts[3 * s + 0], s1 = shifts[3 * s + 1], s2 = shifts[3 * s + 2];
        float svx = s0 * cell[0] + s1 * cell[3] + s2 * cell[6];
        float svy = s0 * cell[1] + s1 * cell[4] + s2 * cell[7];
        float svz = s0 * cell[2] + s1 * cell[5] + s2 * cell[8];

        int rowbase = Pc + (s * n + i) * n;
        const float4* __restrict__ pos4 = (const float4*)pos;
        int nq = n >> 2;

        for (int q = tid; q < nq; q += blockDim.x) {
            float4 a  = pos4[3 * q + 0];
            float4 b  = pos4[3 * q + 1];
            float4 cc = pos4[3 * q + 2];

            float dx, dy, dz;
            float4 dv;
            // reference FP ordering: (pi - pj) + sv
            dx = (pix - a.x) + svx;  dy = (piy - a.y) + svy;  dz = (piz - a.z) + svz;
            dv.x = dx * dx + dy * dy + dz * dz;
            dx = (pix - a.w) + svx;  dy = (piy - b.x) + svy;  dz = (piz - b.y) + svz;
            dv.y = dx * dx + dy * dy + dz * dz;
            dx = (pix - b.z) + svx;  dy = (piy - b.w) + svy;  dz = (piz - cc.x) + svz;
            dv.z = dx * dx + dy * dy + dz * dz;
            dx = (pix - cc.y) + svx; dy = (piy - cc.z) + svy; dz = (piz - cc.w) + svz;
            dv.w = dx * dx + dy * dy + dz * dz;

            int addr = rowbase + 4 * q;
            st_cs_v4(out + addr, dv);

#pragma unroll
            for (int c = 0; c < C; c++) {
                float4 mv;
                mv.x = (dv.x < c2[c]) ? 1.0f : 0.0f;
                mv.y = (dv.y < c2[c]) ? 1.0f : 0.0f;
                mv.z = (dv.z < c2[c]) ? 1.0f : 0.0f;
                mv.w = (dv.w < c2[c]) ? 1.0f : 0.0f;
                st_cs_v4(out + P + c * P + addr, mv);
            }
        }

        // scalar remainder (n % 4 != 0; not hit for n=1000)
        for (int j = (nq << 2) + tid; j < n; j += blockDim.x) {
            float dx = (pix - pos[3 * j + 0]) + svx;
            float dy = (piy - pos[3 * j + 1]) + svy;
            float dz = (piz - pos[3 * j + 2]) + svz;
            float d2 = dx * dx + dy * dy + dz * dz;
            int addr = rowbase + j;
            st_cs_f(out + addr, d2);
#pragma unroll
            for (int c = 0; c < C; c++)
                st_cs_f(out + P + c * P + addr, (d2 < c2[c]) ? 1.0f : 0.0f);
        }
    } else {
        // ------------- triangle pairs, balanced: rows bx and n-2-bx -------------
#pragma unroll 1
        for (int pass = 0; pass < 2; pass++) {
            int i = (pass == 0) ? bx : (n - 2 - bx);
            if (i < 0 || i >= n - 1) continue;
            if (pass == 1 && i <= bx) continue;   // avoid double-handling middle row

            float pix = pos[3 * i + 0];
            float piy = pos[3 * i + 1];
            float piz = pos[3 * i + 2];
            int off = i * (2 * n - i - 1) / 2;    // packed row start

            for (int j = i + 1 + tid; j < n; j += blockDim.x) {
                float dx = pix - pos[3 * j + 0];
                float dy = piy - pos[3 * j + 1];
                float dz = piz - pos[3 * j + 2];
                float d2 = dx * dx + dy * dy + dz * dz;
                int p = off + (j - i - 1);
                st_cs_f(out + p, d2);
#pragma unroll
                for (int c = 0; c < C; c++)
                    st_cs_f(out + P + c * P + p, (d2 < c2[c]) ? 1.0f : 0.0f);
            }
        }
    }
}

extern "C" void kernel_launch(void* const* d_in, const int* in_sizes, int n_in,
                              void* d_out, int out_size)
{
    const float* pos     = (const float*)d_in[0];  // [N,3]
    const float* cell    = (const float*)d_in[1];  // [3,3]
    const float* shifts  = (const float*)d_in[2];  // [S,3]
    const float* cutoffs = (const float*)d_in[3];  // [C]

    int n = in_sizes[0] / 3;
    int S = in_sizes[2] / 3;
    int C = in_sizes[3];

    int Pc = n * (n - 1) / 2;
    int P  = Pc + S * n * n;

    dim3 grid(n, S + 1);
    float* out = (float*)d_out;

    switch (C) {
        case 1: fused_kernel<1><<<grid, 256>>>(pos, cell, shifts, cutoffs, n, S, Pc, P, out); break;
        case 2: fused_kernel<2><<<grid, 256>>>(pos, cell, shifts, cutoffs, n, S, Pc, P, out); break;
        case 3: fused_kernel<3><<<grid, 256>>>(pos, cell, shifts, cutoffs, n, S, Pc, P, out); break;
        default: fused_kernel<4><<<grid, 256>>>(pos, cell, shifts, cutoffs, n, S, Pc, P, out); break;
    }
}

// round 11
// speedup vs baseline: 1.0958x; 1.0145x over previous
#include <cuda_runtime.h>

// PBC neighbor-list distances. Single fused launch (champion R8 shape).
// Output (float32): [ d2[P] | mask_c0[P] | mask_c1[P] | ... ]
//   P = N*(N-1)/2 + S*N*N
// gridDim = (N, S+1): y=s<S shifted row (one float4 j-quad per thread),
//                     y=S triangle row i (scalar, 3.7% of bytes).
// Session evidence (R1-R10): mandatory 162MB write stream pins the kernel at
// ~26.5us regardless of store path (STG.32/128, st.cs, TMA) or math encoding;
// st.global.cs + one-quad-per-thread + 14000 blocks is the measured optimum.
// EXACT4: dead remainder loop removed at compile time when n % 4 == 0.
// All offsets fit in int32 (3P ~ 40.5M).

__device__ __forceinline__ void st_cs_v4(float* p, float4 v) {
    asm volatile("st.global.cs.v4.f32 [%0],{%1,%2,%3,%4};"
                 :: "l"(p), "f"(v.x), "f"(v.y), "f"(v.z), "f"(v.w) : "memory");
}
__device__ __forceinline__ void st_cs_f(float* p, float v) {
    asm volatile("st.global.cs.f32 [%0],%1;" :: "l"(p), "f"(v) : "memory");
}

template <int C, bool EXACT4>
__global__ __launch_bounds__(256)
void fused_kernel(const float* __restrict__ pos,
                  const float* __restrict__ cell,
                  const float* __restrict__ shifts,
                  const float* __restrict__ cutoffs,
                  int n, int S, int Pc, int P,
                  float* __restrict__ out)
{
    int i   = blockIdx.x;
    int s   = blockIdx.y;
    int tid = threadIdx.x;

    float c2[C];
#pragma unroll
    for (int c = 0; c < C; c++) { float cv = __ldg(cutoffs + c); c2[c] = cv * cv; }

    float pix = __ldg(pos + 3 * i + 0);
    float piy = __ldg(pos + 3 * i + 1);
    float piz = __ldg(pos + 3 * i + 2);

    if (s < S) {
        // ---------------- shifted-image row (s, i, :) ----------------
        float s0 = __ldg(shifts + 3 * s + 0);
        float s1 = __ldg(shifts + 3 * s + 1);
        float s2 = __ldg(shifts + 3 * s + 2);
        float svx = s0 * cell[0] + s1 * cell[3] + s2 * cell[6];
        float svy = s0 * cell[1] + s1 * cell[4] + s2 * cell[7];
        float svz = s0 * cell[2] + s1 * cell[5] + s2 * cell[8];

        int rowbase = Pc + (s * n + i) * n;
        const float4* __restrict__ pos4 = (const float4*)pos;
        int nq = n >> 2;

        for (int q = tid; q < nq; q += blockDim.x) {
            float4 a  = pos4[3 * q + 0];
            float4 b  = pos4[3 * q + 1];
            float4 cc = pos4[3 * q + 2];

            float dx, dy, dz;
            float4 dv;
            // reference FP ordering: (pi - pj) + sv
            dx = (pix - a.x) + svx;  dy = (piy - a.y) + svy;  dz = (piz - a.z) + svz;
            dv.x = dx * dx + dy * dy + dz * dz;
            dx = (pix - a.w) + svx;  dy = (piy - b.x) + svy;  dz = (piz - b.y) + svz;
            dv.y = dx * dx + dy * dy + dz * dz;
            dx = (pix - b.z) + svx;  dy = (piy - b.w) + svy;  dz = (piz - cc.x) + svz;
            dv.z = dx * dx + dy * dy + dz * dz;
            dx = (pix - cc.y) + svx; dy = (piy - cc.z) + svy; dz = (piz - cc.w) + svz;
            dv.w = dx * dx + dy * dy + dz * dz;

            int addr = rowbase + 4 * q;
            st_cs_v4(out + addr, dv);

#pragma unroll
            for (int c = 0; c < C; c++) {
                float4 mv;
                mv.x = (dv.x < c2[c]) ? 1.0f : 0.0f;
                mv.y = (dv.y < c2[c]) ? 1.0f : 0.0f;
                mv.z = (dv.z < c2[c]) ? 1.0f : 0.0f;
                mv.w = (dv.w < c2[c]) ? 1.0f : 0.0f;
                st_cs_v4(out + P + c * P + addr, mv);
            }
        }

        if (!EXACT4) {
            // scalar remainder for n % 4 != 0 (compiled out when EXACT4)
            for (int j = (nq << 2) + tid; j < n; j += blockDim.x) {
                float dx = (pix - pos[3 * j + 0]) + svx;
                float dy = (piy - pos[3 * j + 1]) + svy;
                float dz = (piz - pos[3 * j + 2]) + svz;
                float d2 = dx * dx + dy * dy + dz * dz;
                int addr = rowbase + j;
                st_cs_f(out + addr, d2);
#pragma unroll
                for (int c = 0; c < C; c++)
                    st_cs_f(out + P + c * P + addr, (d2 < c2[c]) ? 1.0f : 0.0f);
            }
        }
    } else {
        // ---------------- triangle row i: pairs (i, j), j > i ----------------
        int off = i * (2 * n - i - 1) / 2;   // packed row start
        for (int j = i + 1 + tid; j < n; j += blockDim.x) {
            float dx = pix - pos[3 * j + 0];
            float dy = piy - pos[3 * j + 1];
            float dz = piz - pos[3 * j + 2];
            float d2 = dx * dx + dy * dy + dz * dz;
            int p = off + (j - i - 1);
            st_cs_f(out + p, d2);
#pragma unroll
            for (int c = 0; c < C; c++)
                st_cs_f(out + P + c * P + p, (d2 < c2[c]) ? 1.0f : 0.0f);
        }
    }
}

template <int C>
static void launch_c(dim3 grid, const float* pos, const float* cell,
                     const float* shifts, const float* cutoffs,
                     int n, int S, int Pc, int P, float* out)
{
    if (n % 4 == 0)
        fused_kernel<C, true ><<<grid, 256>>>(pos, cell, shifts, cutoffs, n, S, Pc, P, out);
    else
        fused_kernel<C, false><<<grid, 256>>>(pos, cell, shifts, cutoffs, n, S, Pc, P, out);
}

extern "C" void kernel_launch(void* const* d_in, const int* in_sizes, int n_in,
                              void* d_out, int out_size)
{
    const float* pos     = (const float*)d_in[0];  // [N,3]
    const float* cell    = (const float*)d_in[1];  // [3,3]
    const float* shifts  = (const float*)d_in[2];  // [S,3]
    const float* cutoffs = (const float*)d_in[3];  // [C]

    int n = in_sizes[0] / 3;
    int S = in_sizes[2] / 3;
    int C = in_sizes[3];

    int Pc = n * (n - 1) / 2;
    int P  = Pc + S * n * n;

    dim3 grid(n, S + 1);
    float* out = (float*)d_out;

    switch (C) {
        case 1: launch_c<1>(grid, pos, cell, shifts, cutoffs, n, S, Pc, P, out); break;
        case 2: launch_c<2>(grid, pos, cell, shifts, cutoffs, n, S, Pc, P, out); break;
        case 3: launch_c<3>(grid, pos, cell, shifts, cutoffs, n, S, Pc, P, out); break;
        default: launch_c<4>(grid, pos, cell, shifts, cutoffs, n, S, Pc, P, out); break;
    }
}

// round 12
// speedup vs baseline: 1.0982x; 1.0022x over previous
#include <cuda_runtime.h>

// PBC neighbor-list distances. Single fused launch — session champion (R8).
// Output (float32): [ d2[P] | mask_c0[P] | mask_c1[P] | ... ]
//   P = N*(N-1)/2 + S*N*N
// gridDim = (N, S+1): y=s<S shifted row (one float4 j-quad per thread),
//                     y=S triangle row (scalar, 3.7% of bytes).
//
// Session evidence (R1-R11): the mandatory 162MB output write stream pins the
// kernel at ~26.5us on sm_103a regardless of store path (STG.32/STG.128/
// st.global.cs/TMA bulk), load layout (AoS/SoA), math encoding (scalar/f32x2),
// or work decomposition (1/2 rows per block, balanced triangle). This shape
// (st.cs + one-quad-per-thread + 14000 blocks, regs 32, occ ~85%) is the
// measured optimum; everything added on top of it cost time.
// All offsets fit in int32 (3P ~ 40.5M).

__device__ __forceinline__ void st_cs_v4(float* p, float4 v) {
    asm volatile("st.global.cs.v4.f32 [%0],{%1,%2,%3,%4};"
                 :: "l"(p), "f"(v.x), "f"(v.y), "f"(v.z), "f"(v.w) : "memory");
}
__device__ __forceinline__ void st_cs_f(float* p, float v) {
    asm volatile("st.global.cs.f32 [%0],%1;" :: "l"(p), "f"(v) : "memory");
}

template <int C>
__global__ __launch_bounds__(256)
void fused_kernel(const float* __restrict__ pos,
                  const float* __restrict__ cell,
                  const float* __restrict__ shifts,
                  const float* __restrict__ cutoffs,
                  int n, int S, int Pc, int P,
                  float* __restrict__ out)
{
    int i   = blockIdx.x;
    int s   = blockIdx.y;
    int tid = threadIdx.x;

    float c2[C];
#pragma unroll
    for (int c = 0; c < C; c++) { float cv = cutoffs[c]; c2[c] = cv * cv; }

    float pix = pos[3 * i + 0];
    float piy = pos[3 * i + 1];
    float piz = pos[3 * i + 2];

    if (s < S) {
        // ---------------- shifted-image row (s, i, :) ----------------
        float s0 = shifts[3 * s + 0], s1 = shifts[3 * s + 1], s2 = shifts[3 * s + 2];
        float svx = s0 * cell[0] + s1 * cell[3] + s2 * cell[6];
        float svy = s0 * cell[1] + s1 * cell[4] + s2 * cell[7];
        float svz = s0 * cell[2] + s1 * cell[5] + s2 * cell[8];

        int rowbase = Pc + (s * n + i) * n;
        const float4* __restrict__ pos4 = (const float4*)pos;
        int nq = n >> 2;

        for (int q = tid; q < nq; q += blockDim.x) {
            float4 a  = pos4[3 * q + 0];
            float4 b  = pos4[3 * q + 1];
            float4 cc = pos4[3 * q + 2];

            float dx, dy, dz;
            float4 dv;
            // reference FP ordering: (pi - pj) + sv
            dx = (pix - a.x) + svx;  dy = (piy - a.y) + svy;  dz = (piz - a.z) + svz;
            dv.x = dx * dx + dy * dy + dz * dz;
            dx = (pix - a.w) + svx;  dy = (piy - b.x) + svy;  dz = (piz - b.y) + svz;
            dv.y = dx * dx + dy * dy + dz * dz;
            dx = (pix - b.z) + svx;  dy = (piy - b.w) + svy;  dz = (piz - cc.x) + svz;
            dv.z = dx * dx + dy * dy + dz * dz;
            dx = (pix - cc.y) + svx; dy = (piy - cc.z) + svy; dz = (piz - cc.w) + svz;
            dv.w = dx * dx + dy * dy + dz * dz;

            int addr = rowbase + 4 * q;
            st_cs_v4(out + addr, dv);

#pragma unroll
            for (int c = 0; c < C; c++) {
                float4 mv;
                mv.x = (dv.x < c2[c]) ? 1.0f : 0.0f;
                mv.y = (dv.y < c2[c]) ? 1.0f : 0.0f;
                mv.z = (dv.z < c2[c]) ? 1.0f : 0.0f;
                mv.w = (dv.w < c2[c]) ? 1.0f : 0.0f;
                st_cs_v4(out + P + c * P + addr, mv);
            }
        }

        // scalar remainder (n % 4 != 0; not hit for n=1000)
        for (int j = (nq << 2) + tid; j < n; j += blockDim.x) {
            float dx = (pix - pos[3 * j + 0]) + svx;
            float dy = (piy - pos[3 * j + 1]) + svy;
            float dz = (piz - pos[3 * j + 2]) + svz;
            float d2 = dx * dx + dy * dy + dz * dz;
            int addr = rowbase + j;
            st_cs_f(out + addr, d2);
#pragma unroll
            for (int c = 0; c < C; c++)
                st_cs_f(out + P + c * P + addr, (d2 < c2[c]) ? 1.0f : 0.0f);
        }
    } else {
        // ---------------- triangle row i: pairs (i, j), j > i ----------------
        int off = i * (2 * n - i - 1) / 2;   // packed row start
        for (int j = i + 1 + tid; j < n; j += blockDim.x) {
            float dx = pix - pos[3 * j + 0];
            float dy = piy - pos[3 * j + 1];
            float dz = piz - pos[3 * j + 2];
            float d2 = dx * dx + dy * dy + dz * dz;
            int p = off + (j - i - 1);
            st_cs_f(out + p, d2);
#pragma unroll
            for (int c = 0; c < C; c++)
                st_cs_f(out + P + c * P + p, (d2 < c2[c]) ? 1.0f : 0.0f);
        }
    }
}

extern "C" void kernel_launch(void* const* d_in, const int* in_sizes, int n_in,
                              void* d_out, int out_size)
{
    const float* pos     = (const float*)d_in[0];  // [N,3]
    const float* cell    = (const float*)d_in[1];  // [3,3]
    const float* shifts  = (const float*)d_in[2];  // [S,3]
    const float* cutoffs = (const float*)d_in[3];  // [C]

    int n = in_sizes[0] / 3;
    int S = in_sizes[2] / 3;
    int C = in_sizes[3];

    int Pc = n * (n - 1) / 2;
    int P  = Pc + S * n * n;

    dim3 grid(n, S + 1);
    float* out = (float*)d_out;

    switch (C) {
        case 1: fused_kernel<1><<<grid, 256>>>(pos, cell, shifts, cutoffs, n, S, Pc, P, out); break;
        case 2: fused_kernel<2><<<grid, 256>>>(pos, cell, shifts, cutoffs, n, S, Pc, P, out); break;
        case 3: fused_kernel<3><<<grid, 256>>>(pos, cell, shifts, cutoffs, n, S, Pc, P, out); break;
        default: fused_kernel<4><<<grid, 256>>>(pos, cell, shifts, cutoffs, n, S, Pc, P, out); break;
    }
}

// round 13
// speedup vs baseline: 1.1604x; 1.0566x over previous
#include <cuda_runtime.h>

// PBC neighbor-list distances. Single fused launch — session-final champion.
// Output (float32): [ d2[P] | mask_c0[P] | mask_c1[P] | ... ]
//   P = N*(N-1)/2 + S*N*N
// gridDim = (N, S+1): y=s<S shifted row (one float4 j-quad per thread),
//                     y=S triangle row (scalar, 3.7% of bytes).
//
// Session evidence (R1-R12): the mandatory 162MB output write stream pins the
// kernel at ~26.4us on sm_103a across every store path (STG.32/STG.128/
// st.global.cs/TMA bulk), load layout (AoS/SoA), math encoding (scalar/f32x2)
// and decomposition tried; bench spread beyond that is run noise. This shape
// (st.cs + one-quad-per-thread + 14000 blocks, regs 32, occ ~85%) is the
// measured optimum. ONE_ITER removes the loop bookkeeping when n <= 1024.
// All offsets fit in int32 (3P ~ 40.5M).

__device__ __forceinline__ void st_cs_v4(float* p, float4 v) {
    asm volatile("st.global.cs.v4.f32 [%0],{%1,%2,%3,%4};"
                 :: "l"(p), "f"(v.x), "f"(v.y), "f"(v.z), "f"(v.w) : "memory");
}
__device__ __forceinline__ void st_cs_f(float* p, float v) {
    asm volatile("st.global.cs.f32 [%0],%1;" :: "l"(p), "f"(v) : "memory");
}

template <int C, bool ONE_ITER>
__global__ __launch_bounds__(256)
void fused_kernel(const float* __restrict__ pos,
                  const float* __restrict__ cell,
                  const float* __restrict__ shifts,
                  const float* __restrict__ cutoffs,
                  int n, int S, int Pc, int P,
                  float* __restrict__ out)
{
    int i   = blockIdx.x;
    int s   = blockIdx.y;
    int tid = threadIdx.x;

    float c2[C];
#pragma unroll
    for (int c = 0; c < C; c++) { float cv = cutoffs[c]; c2[c] = cv * cv; }

    float pix = pos[3 * i + 0];
    float piy = pos[3 * i + 1];
    float piz = pos[3 * i + 2];

    if (s < S) {
        // ---------------- shifted-image row (s, i, :) ----------------
        float s0 = shifts[3 * s + 0], s1 = shifts[3 * s + 1], s2 = shifts[3 * s + 2];
        float svx = s0 * cell[0] + s1 * cell[3] + s2 * cell[6];
        float svy = s0 * cell[1] + s1 * cell[4] + s2 * cell[7];
        float svz = s0 * cell[2] + s1 * cell[5] + s2 * cell[8];

        int rowbase = Pc + (s * n + i) * n;
        const float4* __restrict__ pos4 = (const float4*)pos;
        int nq = n >> 2;

        for (int q = tid; q < nq; q += blockDim.x) {
            float4 a  = pos4[3 * q + 0];
            float4 b  = pos4[3 * q + 1];
            float4 cc = pos4[3 * q + 2];

            float dx, dy, dz;
            float4 dv;
            // reference FP ordering: (pi - pj) + sv
            dx = (pix - a.x) + svx;  dy = (piy - a.y) + svy;  dz = (piz - a.z) + svz;
            dv.x = dx * dx + dy * dy + dz * dz;
            dx = (pix - a.w) + svx;  dy = (piy - b.x) + svy;  dz = (piz - b.y) + svz;
            dv.y = dx * dx + dy * dy + dz * dz;
            dx = (pix - b.z) + svx;  dy = (piy - b.w) + svy;  dz = (piz - cc.x) + svz;
            dv.z = dx * dx + dy * dy + dz * dz;
            dx = (pix - cc.y) + svx; dy = (piy - cc.z) + svy; dz = (piz - cc.w) + svz;
            dv.w = dx * dx + dy * dy + dz * dz;

            int addr = rowbase + 4 * q;
            st_cs_v4(out + addr, dv);

#pragma unroll
            for (int c = 0; c < C; c++) {
                float4 mv;
                mv.x = (dv.x < c2[c]) ? 1.0f : 0.0f;
                mv.y = (dv.y < c2[c]) ? 1.0f : 0.0f;
                mv.z = (dv.z < c2[c]) ? 1.0f : 0.0f;
                mv.w = (dv.w < c2[c]) ? 1.0f : 0.0f;
                st_cs_v4(out + P + c * P + addr, mv);
            }

            if (ONE_ITER) break;   // n <= 1024: each thread owns at most one quad
        }

        // scalar remainder (n % 4 != 0; not hit for n=1000)
        for (int j = (nq << 2) + tid; j < n; j += blockDim.x) {
            float dx = (pix - pos[3 * j + 0]) + svx;
            float dy = (piy - pos[3 * j + 1]) + svy;
            float dz = (piz - pos[3 * j + 2]) + svz;
            float d2 = dx * dx + dy * dy + dz * dz;
            int addr = rowbase + j;
            st_cs_f(out + addr, d2);
#pragma unroll
            for (int c = 0; c < C; c++)
                st_cs_f(out + P + c * P + addr, (d2 < c2[c]) ? 1.0f : 0.0f);
        }
    } else {
        // ---------------- triangle row i: pairs (i, j), j > i ----------------
        int off = i * (2 * n - i - 1) / 2;   // packed row start
        for (int j = i + 1 + tid; j < n; j += blockDim.x) {
            float dx = pix - pos[3 * j + 0];
            float dy = piy - pos[3 * j + 1];
            float dz = piz - pos[3 * j + 2];
            float d2 = dx * dx + dy * dy + dz * dz;
            int p = off + (j - i - 1);
            st_cs_f(out + p, d2);
#pragma unroll
            for (int c = 0; c < C; c++)
                st_cs_f(out + P + c * P + p, (d2 < c2[c]) ? 1.0f : 0.0f);
        }
    }
}

template <int C>
static void launch_c(dim3 grid, const float* pos, const float* cell,
                     const float* shifts, const float* cutoffs,
                     int n, int S, int Pc, int P, float* out)
{
    if (n <= 1024)
        fused_kernel<C, true ><<<grid, 256>>>(pos, cell, shifts, cutoffs, n, S, Pc, P, out);
    else
        fused_kernel<C, false><<<grid, 256>>>(pos, cell, shifts, cutoffs, n, S, Pc, P, out);
}

extern "C" void kernel_launch(void* const* d_in, const int* in_sizes, int n_in,
                              void* d_out, int out_size)
{
    const float* pos     = (const float*)d_in[0];  // [N,3]
    const float* cell    = (const float*)d_in[1];  // [3,3]
    const float* shifts  = (const float*)d_in[2];  // [S,3]
    const float* cutoffs = (const float*)d_in[3];  // [C]

    int n = in_sizes[0] / 3;
    int S = in_sizes[2] / 3;
    int C = in_sizes[3];

    int Pc = n * (n - 1) / 2;
    int P  = Pc + S * n * n;

    dim3 grid(n, S + 1);
    float* out = (float*)d_out;

    switch (C) {
        case 1: launch_c<1>(grid, pos, cell, shifts, cutoffs, n, S, Pc, P, out); break;
        case 2: launch_c<2>(grid, pos, cell, shifts, cutoffs, n, S, Pc, P, out); break;
        case 3: launch_c<3>(grid, pos, cell, shifts, cutoffs, n, S, Pc, P, out); break;
        default: launch_c<4>(grid, pos, cell, shifts, cutoffs, n, S, Pc, P, out); break;
    }
}